// round 15
// baseline (speedup 1.0000x reference)
#include <cuda_runtime.h>
#include <cuda_fp16.h>
#include <math.h>
#include <stdint.h>

// ---------------- problem constants ----------------
#define BB   32768
#define HH   128
#define EE   16
#define KK   144          // combined K = H (128) + E (16)
#define NOBS 9
#define NOUT 19

#define MT    128         // batch rows per CTA
#define NCTA  (BB/MT)     // 256
#define NTHR  256         // 8 warps, warp w owns rows 16w..16w+15

// B fragment-linear layout: chunk c (64 gates) -> 8 ntiles x 9 ktiles x 2
// products, each block = 32 lanes x 2 .b32 = 256 B. Chunk = 36864 B.
#define CHUNKB 36864

// ---------------- smem layout (bytes) ----------------
#define SM_WOUT  0                   // 256 f
#define SM_BQ4   1024                // 512 f (bias, j-major quads)
#define SM_E     3072                // 128x16 f32
#define SM_AF    11264               // A fragments: 8mt x 9kt x 512B = 36864
#define SM_B0    48128               // 36864
#define SM_B1    84992               // 36864 -> ends 121856
#define SM_HS    48128               // h staging (64KB), aliased over B0/B1
#define SMEM_SZ  121856

// ---------------- device globals ----------------
__device__ __align__(128) uint32_t g_Bfrag[8 * CHUNKB / 4];  // 73728 .b32
__device__ __align__(128) float g_bq4[512];                  // bias[j][q]
__device__ __align__(128) float g_h[BB * HH];
__device__ __align__(128) float g_c[BB * HH];

// ---------------- helpers ----------------
__device__ __forceinline__ uint32_t s2u(const void* p) {
    uint32_t a;
    asm("{ .reg .u64 t; cvta.to.shared.u64 t, %1; cvt.u32.u64 %0, t; }" : "=r"(a) : "l"(p));
    return a;
}
__device__ __forceinline__ void cp16(uint32_t saddr, const void* g) {
    asm volatile("cp.async.cg.shared.global [%0], [%1], 16;" :: "r"(saddr), "l"(g));
}
#define CP_COMMIT() asm volatile("cp.async.commit_group;" ::: "memory")
template <int N> __device__ __forceinline__ void cp_wait() {
    asm volatile("cp.async.wait_group %0;" :: "n"(N) : "memory");
}
__device__ __forceinline__ void lds128(uint32_t* r, uint32_t a) {
    asm volatile("ld.shared.v4.b32 {%0,%1,%2,%3}, [%4];"
                 : "=r"(r[0]), "=r"(r[1]), "=r"(r[2]), "=r"(r[3]) : "r"(a));
}
__device__ __forceinline__ void lds64(uint32_t* r, uint32_t a) {
    asm volatile("ld.shared.v2.b32 {%0,%1}, [%2];"
                 : "=r"(r[0]), "=r"(r[1]) : "r"(a));
}
__device__ __forceinline__ void mma16816(float* d, const uint32_t* a,
                                         const uint32_t* b) {
    asm volatile(
        "mma.sync.aligned.m16n8k16.row.col.f32.f16.f16.f32 "
        "{%0,%1,%2,%3}, {%4,%5,%6,%7}, {%8,%9}, {%0,%1,%2,%3};"
        : "+f"(d[0]), "+f"(d[1]), "+f"(d[2]), "+f"(d[3])
        : "r"(a[0]), "r"(a[1]), "r"(a[2]), "r"(a[3]), "r"(b[0]), "r"(b[1]));
}
__device__ __forceinline__ uint32_t packh2(float a, float b) {
    __half2 v = __floats2half2_rn(a, b);
    return *reinterpret_cast<uint32_t*>(&v);
}
__device__ __forceinline__ float tanh_hw(float x) {
    float y;
    asm("tanh.approx.f32 %0, %1;" : "=f"(y) : "f"(x));
    return y;
}
__device__ __forceinline__ float fsig(float x) {
    return fmaf(tanh_hw(0.5f * x), 0.5f, 0.5f);
}

// ---------------------------------------------------------------------------
// Prep: pack [W_hh|W_ih] into fragment-linear fp16 hi/lo blocks + quad bias.
// .b32 index: c*9216 + ((t*9+kt)*2+p)*64 + L*2 + r
//   lane L: n = L>>2 (tile col), k = kt*16 + (L&3)*2 + r*8 (+0,+1 packed)
//   gate col n -> quad a=n>>2, gate q=n&3, unit j = c*16 + 2t + a,
//   original weight row = q*128 + j.
// ---------------------------------------------------------------------------
__global__ void prep_kernel(const float* __restrict__ W_ih,
                            const float* __restrict__ b_ih,
                            const float* __restrict__ W_hh,
                            const float* __restrict__ b_hh) {
    int idx = blockIdx.x * blockDim.x + threadIdx.x;
    int stride = gridDim.x * blockDim.x;
    for (int i = idx; i < 8 * CHUNKB / 4; i += stride) {
        int r = i & 1;
        int L = (i >> 1) & 31;
        int p = (i >> 6) & 1;
        int q9 = i >> 7;
        int kt = q9 % 9;
        int q2 = q9 / 9;
        int t = q2 & 7;
        int c = q2 >> 3;
        int n = L >> 2;
        int k = kt * 16 + (L & 3) * 2 + r * 8;
        int a = n >> 2, qd = n & 3;
        int j = c * 16 + 2 * t + a;
        int orow = qd * 128 + j;
        float v0 = (k < HH) ? W_hh[orow * HH + k] : W_ih[orow * EE + (k - HH)];
        float v1 = (k + 1 < HH) ? W_hh[orow * HH + k + 1]
                                : W_ih[orow * EE + (k + 1 - HH)];
        __half h0 = __float2half_rn(v0), h1 = __float2half_rn(v1);
        if (p == 1) {   // lo residual
            h0 = __float2half_rn(v0 - __half2float(h0));
            h1 = __float2half_rn(v1 - __half2float(h1));
        }
        __half2 hv = __halves2half2(h0, h1);
        g_Bfrag[i] = *reinterpret_cast<uint32_t*>(&hv);
    }
    for (int i = idx; i < 512; i += stride) {
        int j = i >> 2, q = i & 3;
        g_bq4[i] = b_ih[q * 128 + j] + b_hh[q * 128 + j];
    }
}

// ---------------------------------------------------------------------------
// One LSTM step via warp-level mma.sync (m16n8k16 fp16, fp32 accum).
// ---------------------------------------------------------------------------
__global__ void __launch_bounds__(NTHR, 1)
lstm_step(const float* __restrict__ dA, const float* __restrict__ dB,
          float* __restrict__ outp,
          const float* __restrict__ W_emb, const float* __restrict__ b_emb,
          const float* __restrict__ W_out, const float* __restrict__ b_out,
          int is_first) {
    extern __shared__ unsigned char smem[];
    const uint32_t sbase = s2u(smem);
    const int tid = threadIdx.x;
    const int w = tid >> 5, L = tid & 31;
    const int m0 = blockIdx.x * MT;

    float* wout_s = (float*)(smem + SM_WOUT);
    float* bq4_s  = (float*)(smem + SM_BQ4);
    float* e_s    = (float*)(smem + SM_E);
    float* hs_s   = (float*)(smem + SM_HS);

    // stage constants
    for (int i = tid; i < 256; i += NTHR) wout_s[i] = W_out[i];
    for (int i = tid; i < 512; i += NTHR) bq4_s[i] = g_bq4[i];

    // embeddings e = relu(W_emb @ delta + b_emb)  (fp32 in smem)
    if (tid < MT) {
        int grow = m0 + tid;
        float dx = dA[grow * 2 + 0] - dB[grow * 2 + 0];
        float dy = dA[grow * 2 + 1] - dB[grow * 2 + 1];
        #pragma unroll
        for (int ei = 0; ei < EE; ei++) {
            float v = fmaf(W_emb[ei * 2 + 0], dx,
                      fmaf(W_emb[ei * 2 + 1], dy, b_emb[ei]));
            e_s[tid * EE + ei] = fmaxf(v, 0.0f);
        }
    }
    // stage h tile fp32 (coalesced); zeros on first step
    if (is_first) {
        for (int i = tid; i < MT * HH / 4; i += NTHR)
            ((float4*)hs_s)[i] = make_float4(0.f, 0.f, 0.f, 0.f);
    } else {
        const float4* src = (const float4*)(g_h + (size_t)m0 * HH);
        for (int i = tid; i < MT * HH / 4; i += NTHR)
            ((float4*)hs_s)[i] = src[i];
    }
    __syncthreads();

    // build A fragments (fp16), fragment-linear: (mt,kt) block 512B,
    // lane L2 4 regs. reg r: row += (r&1)*8, k += (r>>1)*8.
    for (int idx = tid; idx < 9216; idx += NTHR) {
        int r = idx & 3;
        int L2 = (idx >> 2) & 31;
        int kt = (idx >> 7) % 9;
        int mt = idx / (128 * 9);
        int row = mt * 16 + (L2 >> 2) + (r & 1) * 8;
        int k0 = kt * 16 + (L2 & 3) * 2 + (r >> 1) * 8;
        float v0, v1;
        if (k0 < HH) {
            v0 = hs_s[row * HH + k0];
            v1 = hs_s[row * HH + k0 + 1];
        } else {
            v0 = e_s[row * EE + (k0 - HH)];
            v1 = e_s[row * EE + (k0 - HH) + 1];
        }
        ((uint32_t*)(smem + SM_AF))[(mt * 9 + kt) * 128 + L2 * 4 + r] =
            packh2(v0, v1);
    }
    __syncthreads();   // hs_s dead; B buffers may now be filled

    // prefetch B chunk 0
    {
        const unsigned char* src = (const unsigned char*)g_Bfrag;
        for (int i = tid; i < CHUNKB / 16; i += NTHR)
            cp16(sbase + SM_B0 + i * 16, src + i * 16);
        CP_COMMIT();
    }

    // lane geometry
    const int a_lane = (L & 3) >> 1;            // quad index within ntile
    const int odd = L & 1;                      // 0: row g (i,f own); 1: row g+8
    const int row_lane = m0 + w * 16 + (L >> 2) + odd * 8;
    const uint32_t afw = sbase + SM_AF + (uint32_t)(w * 9) * 512 + L * 16;
    float s0 = 0.0f, s1 = 0.0f;

    for (int c = 0; c < 8; c++) {
        if (c + 1 < 8) {
            const unsigned char* src =
                (const unsigned char*)g_Bfrag + (c + 1) * CHUNKB;
            uint32_t dst = sbase + (((c + 1) & 1) ? SM_B1 : SM_B0);
            for (int i = tid; i < CHUNKB / 16; i += NTHR)
                cp16(dst + i * 16, src + i * 16);
            CP_COMMIT();
            cp_wait<1>();
        } else {
            cp_wait<0>();
        }
        __syncthreads();

        // preload this chunk's c-state (8 scattered LDG, hidden under GEMM)
        float creg[8];
        #pragma unroll
        for (int u = 0; u < 8; u++) {
            int j = c * 16 + 2 * u + a_lane;
            creg[u] = is_first ? 0.0f
                               : g_c[(size_t)row_lane * HH + j];
        }

        const uint32_t bb = sbase + ((c & 1) ? SM_B1 : SM_B0);
        #pragma unroll
        for (int tg = 0; tg < 2; tg++) {
            float D[4][4];
            #pragma unroll
            for (int t = 0; t < 4; t++)
                #pragma unroll
                for (int q = 0; q < 4; q++) D[t][q] = 0.0f;

            #pragma unroll
            for (int kt = 0; kt < 9; kt++) {
                uint32_t a[4];
                lds128(a, afw + kt * 512);
                #pragma unroll
                for (int p = 0; p < 2; p++) {
                    #pragma unroll
                    for (int t = 0; t < 4; t++) {
                        int nt = tg * 4 + t;
                        uint32_t b[2];
                        lds64(b, bb + (uint32_t)(((nt * 9 + kt) * 2 + p) * 256)
                                  + L * 8);
                        mma16816(D[t], a, b);
                    }
                }
            }
            // epilogue: quad exchange + cell update (1 unit-row per lane/tile)
            #pragma unroll
            for (int t = 0; t < 4; t++) {
                int nt = tg * 4 + t;
                int j = c * 16 + 2 * nt + a_lane;
                float e0 = __shfl_xor_sync(0xFFFFFFFFu, D[t][0], 1);
                float e1 = __shfl_xor_sync(0xFFFFFFFFu, D[t][1], 1);
                float e2 = __shfl_xor_sync(0xFFFFFFFFu, D[t][2], 1);
                float e3 = __shfl_xor_sync(0xFFFFFFFFu, D[t][3], 1);
                float gi = odd ? e2 : D[t][0];
                float gf = odd ? e3 : D[t][1];
                float gg = odd ? D[t][2] : e0;
                float go = odd ? D[t][3] : e1;
                float4 bq = *(const float4*)(bq4_s + j * 4);
                float iv = fsig(gi + bq.x);
                float fv = fsig(gf + bq.y);
                float gv = tanh_hw(gg + bq.z);
                float ov = fsig(go + bq.w);
                float c2 = fmaf(fv, creg[tg * 4 + t], iv * gv);
                float h2 = ov * tanh_hw(c2);
                size_t gidx = (size_t)row_lane * HH + j;
                g_c[gidx] = c2;
                g_h[gidx] = h2;
                s0 = fmaf(h2, wout_s[j], s0);
                s1 = fmaf(h2, wout_s[128 + j], s1);
            }
        }
        __syncthreads();   // all warps done with this chunk's B buffer
    }

    // readout: combine the two lanes (a=0/a=1) sharing a row, then write
    s0 += __shfl_xor_sync(0xFFFFFFFFu, s0, 2);
    s1 += __shfl_xor_sync(0xFFFFFFFFu, s1, 2);
    if ((L & 3) < 2) {
        outp[row_lane * 2 + 0] = dA[row_lane * 2 + 0] + s0 + b_out[0];
        outp[row_lane * 2 + 1] = dA[row_lane * 2 + 1] + s1 + b_out[1];
    }
}

// ---------------------------------------------------------------------------
extern "C" void kernel_launch(void* const* d_in, const int* in_sizes, int n_in,
                              void* d_out, int out_size) {
    const float* observed = (const float*)d_in[0];
    const float* W_emb    = (const float*)d_in[1];
    const float* b_emb    = (const float*)d_in[2];
    const float* W_ih     = (const float*)d_in[3];
    const float* b_ih     = (const float*)d_in[4];
    const float* W_hh     = (const float*)d_in[5];
    const float* b_hh     = (const float*)d_in[6];
    const float* W_out    = (const float*)d_in[7];
    const float* b_out    = (const float*)d_in[8];
    float* out = (float*)d_out;

    static bool attr_set = false;
    if (!attr_set) {
        cudaFuncSetAttribute(lstm_step,
                             cudaFuncAttributeMaxDynamicSharedMemorySize, SMEM_SZ);
        attr_set = true;
    }

    prep_kernel<<<96, 256>>>(W_ih, b_ih, W_hh, b_hh);

    const size_t rs = (size_t)BB * 2;
    // observation phase: t = 1..8 -> out rows 0..7
    for (int t = 1; t < NOBS; t++) {
        lstm_step<<<NCTA, NTHR, SMEM_SZ>>>(
            observed + (size_t)t * rs, observed + (size_t)(t - 1) * rs,
            out + (size_t)(t - 1) * rs,
            W_emb, b_emb, W_out, b_out, (t == 1) ? 1 : 0);
    }
    // prediction phase: out rows 8..18
    for (int r = NOBS - 1; r < NOUT; r++) {
        lstm_step<<<NCTA, NTHR, SMEM_SZ>>>(
            out + (size_t)(r - 1) * rs, out + (size_t)(r - 2) * rs,
            out + (size_t)r * rs,
            W_emb, b_emb, W_out, b_out, 0);
    }
}

// round 16
// speedup vs baseline: 1.0027x; 1.0027x over previous
#include <cuda_runtime.h>
#include <cuda_fp16.h>
#include <math.h>
#include <stdint.h>

// ---------------- problem constants ----------------
#define BB   32768
#define HH   128
#define EE   16
#define KK   144          // combined K = H (128) + E (16)
#define NOBS 9
#define NOUT 19

#define MT    256         // batch rows per CTA
#define NCTA  (BB/MT)     // 128 -> single wave on 148 SMs
#define NTHR  512         // 16 warps, warp w owns rows 16w..16w+15

// B fragment-linear layout: chunk c (64 gates) -> 8 ntiles x 9 ktiles blocks,
// each block = 32 lanes x 4 .b32 (hi0,hi1,lo0,lo1) = 512 B. Chunk = 36864 B.
#define CHUNKB 36864

// ---------------- smem layout (bytes) ----------------
#define SM_WOUT  0                   // 256 f
#define SM_BQ4   1024                // 512 f (bias, j-major quads)
#define SM_E     3072                // 256x16 f32 = 16384
#define SM_AF    19456               // A fragments: 16mt x 9kt x 512B = 73728
#define SM_B0    93184               // 36864
#define SM_B1    130048              // 36864 -> ends 166912
#define SM_HS    93184               // h staging (256x128 f32 = 131072), aliased
#define SMEM_SZ  224256              // = SM_HS + 131072

// ---------------- device globals ----------------
__device__ __align__(128) uint32_t g_Bfrag[8 * CHUNKB / 4];  // 73728 .b32
__device__ __align__(128) float g_bq4[512];                  // bias[j][q]
__device__ __align__(128) float g_h[BB * HH];
__device__ __align__(128) float g_c[BB * HH];

// ---------------- helpers ----------------
__device__ __forceinline__ uint32_t s2u(const void* p) {
    uint32_t a;
    asm("{ .reg .u64 t; cvta.to.shared.u64 t, %1; cvt.u32.u64 %0, t; }" : "=r"(a) : "l"(p));
    return a;
}
__device__ __forceinline__ void cp16(uint32_t saddr, const void* g) {
    asm volatile("cp.async.cg.shared.global [%0], [%1], 16;" :: "r"(saddr), "l"(g));
}
#define CP_COMMIT() asm volatile("cp.async.commit_group;" ::: "memory")
template <int N> __device__ __forceinline__ void cp_wait() {
    asm volatile("cp.async.wait_group %0;" :: "n"(N) : "memory");
}
__device__ __forceinline__ void lds128(uint32_t* r, uint32_t a) {
    asm volatile("ld.shared.v4.b32 {%0,%1,%2,%3}, [%4];"
                 : "=r"(r[0]), "=r"(r[1]), "=r"(r[2]), "=r"(r[3]) : "r"(a));
}
__device__ __forceinline__ void mma16816(float* d, const uint32_t* a,
                                         const uint32_t* b) {
    asm volatile(
        "mma.sync.aligned.m16n8k16.row.col.f32.f16.f16.f32 "
        "{%0,%1,%2,%3}, {%4,%5,%6,%7}, {%8,%9}, {%0,%1,%2,%3};"
        : "+f"(d[0]), "+f"(d[1]), "+f"(d[2]), "+f"(d[3])
        : "r"(a[0]), "r"(a[1]), "r"(a[2]), "r"(a[3]), "r"(b[0]), "r"(b[1]));
}
__device__ __forceinline__ uint32_t packh2(float a, float b) {
    __half2 v = __floats2half2_rn(a, b);
    return *reinterpret_cast<uint32_t*>(&v);
}
__device__ __forceinline__ float tanh_hw(float x) {
    float y;
    asm("tanh.approx.f32 %0, %1;" : "=f"(y) : "f"(x));
    return y;
}
__device__ __forceinline__ float fsig(float x) {
    return fmaf(tanh_hw(0.5f * x), 0.5f, 0.5f);
}

// ---------------------------------------------------------------------------
// Prep: pack [W_hh|W_ih] into fragment-linear fp16 blocks, hi/lo adjacent
// per lane: .b32 index = c*9216 + (nt*9+kt)*128 + L*4 + p*2 + r.
//   lane L: n = L>>2 (tile col), k = kt*16 + (L&3)*2 + r*8 (+0,+1 packed)
//   gate col n -> quad a=n>>2, gate q=n&3, unit j = c*16 + 2*nt + a,
//   original weight row = q*128 + j.  p=0: fp16 hi, p=1: residual lo.
// ---------------------------------------------------------------------------
__global__ void prep_kernel(const float* __restrict__ W_ih,
                            const float* __restrict__ b_ih,
                            const float* __restrict__ W_hh,
                            const float* __restrict__ b_hh) {
    int idx = blockIdx.x * blockDim.x + threadIdx.x;
    int stride = gridDim.x * blockDim.x;
    for (int i = idx; i < 8 * CHUNKB / 4; i += stride) {
        int r = i & 1;
        int p = (i >> 1) & 1;
        int L = (i >> 2) & 31;
        int blk = i >> 7;          // c*72 + nt*9 + kt
        int kt = blk % 9;
        int ntc = blk / 9;
        int nt = ntc & 7;
        int c = ntc >> 3;
        int n = L >> 2;
        int k = kt * 16 + (L & 3) * 2 + r * 8;
        int a = n >> 2, qd = n & 3;
        int j = c * 16 + 2 * nt + a;
        int orow = qd * 128 + j;
        float v0 = (k < HH) ? W_hh[orow * HH + k] : W_ih[orow * EE + (k - HH)];
        float v1 = (k + 1 < HH) ? W_hh[orow * HH + k + 1]
                                : W_ih[orow * EE + (k + 1 - HH)];
        __half h0 = __float2half_rn(v0), h1 = __float2half_rn(v1);
        if (p == 1) {   // lo residual
            h0 = __float2half_rn(v0 - __half2float(h0));
            h1 = __float2half_rn(v1 - __half2float(h1));
        }
        __half2 hv = __halves2half2(h0, h1);
        g_Bfrag[i] = *reinterpret_cast<uint32_t*>(&hv);
    }
    for (int i = idx; i < 512; i += stride) {
        int j = i >> 2, q = i & 3;
        g_bq4[i] = b_ih[q * 128 + j] + b_hh[q * 128 + j];
    }
}

// ---------------------------------------------------------------------------
// One LSTM step via warp-level mma.sync (m16n8k16 fp16, fp32 accum).
// 16 warps, 256 rows/CTA, single wave of 128 CTAs.
// ---------------------------------------------------------------------------
__global__ void __launch_bounds__(NTHR, 1)
lstm_step(const float* __restrict__ dA, const float* __restrict__ dB,
          float* __restrict__ outp,
          const float* __restrict__ W_emb, const float* __restrict__ b_emb,
          const float* __restrict__ W_out, const float* __restrict__ b_out,
          int is_first) {
    extern __shared__ unsigned char smem[];
    const uint32_t sbase = s2u(smem);
    const int tid = threadIdx.x;
    const int w = tid >> 5, L = tid & 31;
    const int m0 = blockIdx.x * MT;

    float* wout_s = (float*)(smem + SM_WOUT);
    float* bq4_s  = (float*)(smem + SM_BQ4);
    float* e_s    = (float*)(smem + SM_E);
    float* hs_s   = (float*)(smem + SM_HS);

    // stage constants
    for (int i = tid; i < 256; i += NTHR) wout_s[i] = W_out[i];
    for (int i = tid; i < 512; i += NTHR) bq4_s[i] = g_bq4[i];

    // embeddings e = relu(W_emb @ delta + b_emb)  (fp32 in smem)
    if (tid < MT) {
        int grow = m0 + tid;
        float dx = dA[grow * 2 + 0] - dB[grow * 2 + 0];
        float dy = dA[grow * 2 + 1] - dB[grow * 2 + 1];
        #pragma unroll
        for (int ei = 0; ei < EE; ei++) {
            float v = fmaf(W_emb[ei * 2 + 0], dx,
                      fmaf(W_emb[ei * 2 + 1], dy, b_emb[ei]));
            e_s[tid * EE + ei] = fmaxf(v, 0.0f);
        }
    }
    // stage h tile fp32 (coalesced); zeros on first step
    if (is_first) {
        for (int i = tid; i < MT * HH / 4; i += NTHR)
            ((float4*)hs_s)[i] = make_float4(0.f, 0.f, 0.f, 0.f);
    } else {
        const float4* src = (const float4*)(g_h + (size_t)m0 * HH);
        for (int i = tid; i < MT * HH / 4; i += NTHR)
            ((float4*)hs_s)[i] = src[i];
    }
    __syncthreads();

    // build A fragments (fp16), fragment-linear: (mt,kt) block 512B,
    // lane L2 has 4 regs. reg r: row += (r&1)*8, k += (r>>1)*8.
    for (int idx = tid; idx < 16 * 9 * 128; idx += NTHR) {
        int r = idx & 3;
        int L2 = (idx >> 2) & 31;
        int kt = (idx >> 7) % 9;
        int mt = idx / (128 * 9);
        int row = mt * 16 + (L2 >> 2) + (r & 1) * 8;
        int k0 = kt * 16 + (L2 & 3) * 2 + (r >> 1) * 8;
        float v0, v1;
        if (k0 < HH) {
            v0 = hs_s[row * HH + k0];
            v1 = hs_s[row * HH + k0 + 1];
        } else {
            v0 = e_s[row * EE + (k0 - HH)];
            v1 = e_s[row * EE + (k0 - HH) + 1];
        }
        ((uint32_t*)(smem + SM_AF))[(mt * 9 + kt) * 128 + L2 * 4 + r] =
            packh2(v0, v1);
    }
    __syncthreads();   // hs_s dead; B buffers may now be filled

    // prefetch B chunk 0
    {
        const unsigned char* src = (const unsigned char*)g_Bfrag;
        for (int i = tid; i < CHUNKB / 16; i += NTHR)
            cp16(sbase + SM_B0 + i * 16, src + i * 16);
        CP_COMMIT();
    }

    // lane geometry
    const int a_lane = (L & 3) >> 1;            // quad index within ntile
    const int odd = L & 1;                      // 0: rows g (i,f own); 1: g+8
    const int row_lane = m0 + w * 16 + (L >> 2) + odd * 8;
    const uint32_t afw = sbase + SM_AF + (uint32_t)(w * 9) * 512 + L * 16;
    float s0 = 0.0f, s1 = 0.0f;

    for (int c = 0; c < 8; c++) {
        if (c + 1 < 8) {
            const unsigned char* src =
                (const unsigned char*)g_Bfrag + (c + 1) * CHUNKB;
            uint32_t dst = sbase + (((c + 1) & 1) ? SM_B1 : SM_B0);
            for (int i = tid; i < CHUNKB / 16; i += NTHR)
                cp16(dst + i * 16, src + i * 16);
            CP_COMMIT();
            cp_wait<1>();
        } else {
            cp_wait<0>();
        }
        __syncthreads();

        // preload this chunk's c-state (8 scattered LDG, hidden under GEMM)
        float creg[8];
        #pragma unroll
        for (int u = 0; u < 8; u++) {
            int j = c * 16 + 2 * u + a_lane;
            creg[u] = is_first ? 0.0f : g_c[(size_t)row_lane * HH + j];
        }

        const uint32_t bb = sbase + ((c & 1) ? SM_B1 : SM_B0);
        #pragma unroll
        for (int tg = 0; tg < 2; tg++) {
            float D[4][4];
            #pragma unroll
            for (int t = 0; t < 4; t++)
                #pragma unroll
                for (int q = 0; q < 4; q++) D[t][q] = 0.0f;

            #pragma unroll
            for (int kt = 0; kt < 9; kt++) {
                uint32_t a[4];
                lds128(a, afw + kt * 512);
                #pragma unroll
                for (int t = 0; t < 4; t++) {
                    int nt = tg * 4 + t;
                    uint32_t b4[4];     // [hi0,hi1,lo0,lo1] for this lane
                    lds128(b4, bb + (uint32_t)((nt * 9 + kt) * 512) + L * 16);
                    mma16816(D[t], a, b4);        // hi product
                    mma16816(D[t], a, b4 + 2);    // lo product
                }
            }
            // epilogue: quad exchange + cell update (1 unit-row per lane/tile)
            #pragma unroll
            for (int t = 0; t < 4; t++) {
                int nt = tg * 4 + t;
                int j = c * 16 + 2 * nt + a_lane;
                float e0 = __shfl_xor_sync(0xFFFFFFFFu, D[t][0], 1);
                float e1 = __shfl_xor_sync(0xFFFFFFFFu, D[t][1], 1);
                float e2 = __shfl_xor_sync(0xFFFFFFFFu, D[t][2], 1);
                float e3 = __shfl_xor_sync(0xFFFFFFFFu, D[t][3], 1);
                float gi = odd ? e2 : D[t][0];
                float gf = odd ? e3 : D[t][1];
                float gg = odd ? D[t][2] : e0;
                float go = odd ? D[t][3] : e1;
                float4 bq = *(const float4*)(bq4_s + j * 4);
                float iv = fsig(gi + bq.x);
                float fv = fsig(gf + bq.y);
                float gv = tanh_hw(gg + bq.z);
                float ov = fsig(go + bq.w);
                float c2 = fmaf(fv, creg[tg * 4 + t], iv * gv);
                float h2 = ov * tanh_hw(c2);
                size_t gidx = (size_t)row_lane * HH + j;
                g_c[gidx] = c2;
                g_h[gidx] = h2;
                s0 = fmaf(h2, wout_s[j], s0);
                s1 = fmaf(h2, wout_s[128 + j], s1);
            }
        }
        __syncthreads();   // all warps done with this chunk's B buffer
    }

    // readout: combine the two lanes (a=0/a=1) sharing a row, then write
    s0 += __shfl_xor_sync(0xFFFFFFFFu, s0, 2);
    s1 += __shfl_xor_sync(0xFFFFFFFFu, s1, 2);
    if ((L & 3) < 2) {
        outp[row_lane * 2 + 0] = dA[row_lane * 2 + 0] + s0 + b_out[0];
        outp[row_lane * 2 + 1] = dA[row_lane * 2 + 1] + s1 + b_out[1];
    }
}

// ---------------------------------------------------------------------------
extern "C" void kernel_launch(void* const* d_in, const int* in_sizes, int n_in,
                              void* d_out, int out_size) {
    const float* observed = (const float*)d_in[0];
    const float* W_emb    = (const float*)d_in[1];
    const float* b_emb    = (const float*)d_in[2];
    const float* W_ih     = (const float*)d_in[3];
    const float* b_ih     = (const float*)d_in[4];
    const float* W_hh     = (const float*)d_in[5];
    const float* b_hh     = (const float*)d_in[6];
    const float* W_out    = (const float*)d_in[7];
    const float* b_out    = (const float*)d_in[8];
    float* out = (float*)d_out;

    static bool attr_set = false;
    if (!attr_set) {
        cudaFuncSetAttribute(lstm_step,
                             cudaFuncAttributeMaxDynamicSharedMemorySize, SMEM_SZ);
        attr_set = true;
    }

    prep_kernel<<<96, 256>>>(W_ih, b_ih, W_hh, b_hh);

    const size_t rs = (size_t)BB * 2;
    // observation phase: t = 1..8 -> out rows 0..7
    for (int t = 1; t < NOBS; t++) {
        lstm_step<<<NCTA, NTHR, SMEM_SZ>>>(
            observed + (size_t)t * rs, observed + (size_t)(t - 1) * rs,
            out + (size_t)(t - 1) * rs,
            W_emb, b_emb, W_out, b_out, (t == 1) ? 1 : 0);
    }
    // prediction phase: out rows 8..18
    for (int r = NOBS - 1; r < NOUT; r++) {
        lstm_step<<<NCTA, NTHR, SMEM_SZ>>>(
            out + (size_t)(r - 1) * rs, out + (size_t)(r - 2) * rs,
            out + (size_t)r * rs,
            W_emb, b_emb, W_out, b_out, 0);
    }
}

// round 17
// speedup vs baseline: 2.0714x; 2.0658x over previous
#include <cuda_runtime.h>
#include <cuda_fp16.h>
#include <math.h>
#include <stdint.h>

// ---------------- problem constants ----------------
#define BB   32768
#define HH   128
#define EE   16
#define KK   144          // combined K = H (128) + E (16)
#define NOBS 9
#define NOUT 19

#define MT    256         // batch rows per CTA
#define NCTA  (BB/MT)     // 128 -> single wave on 148 SMs
#define NTHR  512         // 16 warps, warp w owns rows 16w..16w+15

// B fragment-linear (single fp16 product): chunk c (64 gates) ->
// 4 ntile-pairs x 9 ktiles blocks, each block = 32 lanes x 4 .b32
// [ntEven k0,k8 | ntOdd k0,k8] = 512 B. Chunk = 4*9*512 = 18432 B.
#define CHUNKB 18432

// ---------------- smem layout (bytes) ----------------
#define SM_WOUT  0                   // 256 f
#define SM_BQ4   1024                // 512 f (bias, j-major quads)
#define SM_E     3072                // 256x16 f32 = 16384
#define SM_AF    19456               // A fragments: 16mt x 9kt x 512B = 73728
#define SM_B0    93184               // 18432
#define SM_B1    111616              // 18432 -> ends 130048
#define SM_HS    93184               // h staging (256x128 f32 = 131072), aliased
#define SMEM_SZ  224256              // = SM_HS + 131072

// ---------------- device globals ----------------
__device__ __align__(128) uint32_t g_Bfrag[8 * CHUNKB / 4];  // 36864 .b32
__device__ __align__(128) float g_bq4[512];                  // bias[j][q]
// h/c state in LANE-PERMUTED layout:
//   idx = m0*HH + (c*8 + nt)*512 + w*32 + L   (nt = tg*4+t)
__device__ __align__(128) float g_h[BB * HH];
__device__ __align__(128) float g_c[BB * HH];

// ---------------- helpers ----------------
__device__ __forceinline__ uint32_t s2u(const void* p) {
    uint32_t a;
    asm("{ .reg .u64 t; cvta.to.shared.u64 t, %1; cvt.u32.u64 %0, t; }" : "=r"(a) : "l"(p));
    return a;
}
__device__ __forceinline__ void cp16(uint32_t saddr, const void* g) {
    asm volatile("cp.async.cg.shared.global [%0], [%1], 16;" :: "r"(saddr), "l"(g));
}
#define CP_COMMIT() asm volatile("cp.async.commit_group;" ::: "memory")
template <int N> __device__ __forceinline__ void cp_wait() {
    asm volatile("cp.async.wait_group %0;" :: "n"(N) : "memory");
}
__device__ __forceinline__ void lds128(uint32_t* r, uint32_t a) {
    asm volatile("ld.shared.v4.b32 {%0,%1,%2,%3}, [%4];"
                 : "=r"(r[0]), "=r"(r[1]), "=r"(r[2]), "=r"(r[3]) : "r"(a));
}
__device__ __forceinline__ void mma16816(float* d, const uint32_t* a,
                                         const uint32_t* b) {
    asm volatile(
        "mma.sync.aligned.m16n8k16.row.col.f32.f16.f16.f32 "
        "{%0,%1,%2,%3}, {%4,%5,%6,%7}, {%8,%9}, {%0,%1,%2,%3};"
        : "+f"(d[0]), "+f"(d[1]), "+f"(d[2]), "+f"(d[3])
        : "r"(a[0]), "r"(a[1]), "r"(a[2]), "r"(a[3]), "r"(b[0]), "r"(b[1]));
}
__device__ __forceinline__ uint32_t packh2(float a, float b) {
    __half2 v = __floats2half2_rn(a, b);
    return *reinterpret_cast<uint32_t*>(&v);
}
__device__ __forceinline__ float tanh_hw(float x) {
    float y;
    asm("tanh.approx.f32 %0, %1;" : "=f"(y) : "f"(x));
    return y;
}
__device__ __forceinline__ float fsig(float x) {
    return fmaf(tanh_hw(0.5f * x), 0.5f, 0.5f);
}

// inverse permutation: smem index of h[row_local][k] within the staged block
__device__ __forceinline__ int hperm(int row, int k) {
    int wq = row >> 4, rl = row & 15;
    int od = rl >> 3, rr = rl & 7;
    int cc = k >> 4, rem = k & 15;
    int nt = rem >> 1, al = rem & 1;
    int Lx = rr * 4 + al * 2 + od;
    return (cc * 8 + nt) * 512 + wq * 32 + Lx;
}

// ---------------------------------------------------------------------------
// Prep: pack [W_hh|W_ih] into fragment-linear fp16 blocks (single product).
// .b32 index: c*4608 + (ntp*9+kt)*128 + L*4 + e*2 + r   (nt = ntp*2+e)
//   lane L: n = L>>2 (tile col), k = kt*16 + (L&3)*2 + r*8 (+0,+1 packed)
//   gate col n -> quad a=n>>2, gate q=n&3, unit j = c*16 + 2*nt + a,
//   original weight row = q*128 + j.
// ---------------------------------------------------------------------------
__global__ void prep_kernel(const float* __restrict__ W_ih,
                            const float* __restrict__ b_ih,
                            const float* __restrict__ W_hh,
                            const float* __restrict__ b_hh) {
    int idx = blockIdx.x * blockDim.x + threadIdx.x;
    int stride = gridDim.x * blockDim.x;
    for (int i = idx; i < 8 * CHUNKB / 4; i += stride) {
        int r = i & 1;
        int e = (i >> 1) & 1;
        int L = (i >> 2) & 31;
        int blk = i >> 7;          // c*36 + ntp*9 + kt
        int kt = blk % 9;
        int ntpc = blk / 9;
        int ntp = ntpc & 3;
        int c = ntpc >> 2;
        int nt = ntp * 2 + e;
        int n = L >> 2;
        int k = kt * 16 + (L & 3) * 2 + r * 8;
        int a = n >> 2, qd = n & 3;
        int j = c * 16 + 2 * nt + a;
        int orow = qd * 128 + j;
        float v0 = (k < HH) ? W_hh[orow * HH + k] : W_ih[orow * EE + (k - HH)];
        float v1 = (k + 1 < HH) ? W_hh[orow * HH + k + 1]
                                : W_ih[orow * EE + (k + 1 - HH)];
        __half2 hv = __halves2half2(__float2half_rn(v0), __float2half_rn(v1));
        g_Bfrag[i] = *reinterpret_cast<uint32_t*>(&hv);
    }
    for (int i = idx; i < 512; i += stride) {
        int j = i >> 2, q = i & 3;
        g_bq4[i] = b_ih[q * 128 + j] + b_hh[q * 128 + j];
    }
}

// ---------------------------------------------------------------------------
// One LSTM step via warp-level mma.sync (m16n8k16 fp16, fp32 accum).
// 16 warps, 256 rows/CTA, single wave. h/c in lane-permuted gmem layout so
// ALL state loads/stores are warp-coalesced.
// ---------------------------------------------------------------------------
__global__ void __launch_bounds__(NTHR, 1)
lstm_step(const float* __restrict__ dA, const float* __restrict__ dB,
          float* __restrict__ outp,
          const float* __restrict__ W_emb, const float* __restrict__ b_emb,
          const float* __restrict__ W_out, const float* __restrict__ b_out,
          int is_first) {
    extern __shared__ unsigned char smem[];
    const uint32_t sbase = s2u(smem);
    const int tid = threadIdx.x;
    const int w = tid >> 5, L = tid & 31;
    const int m0 = blockIdx.x * MT;

    float* wout_s = (float*)(smem + SM_WOUT);
    float* bq4_s  = (float*)(smem + SM_BQ4);
    float* e_s    = (float*)(smem + SM_E);
    float* hs_s   = (float*)(smem + SM_HS);

    // stage constants
    for (int i = tid; i < 256; i += NTHR) wout_s[i] = W_out[i];
    for (int i = tid; i < 512; i += NTHR) bq4_s[i] = g_bq4[i];

    // embeddings e = relu(W_emb @ delta + b_emb)  (fp32 in smem)
    if (tid < MT) {
        int grow = m0 + tid;
        float dx = dA[grow * 2 + 0] - dB[grow * 2 + 0];
        float dy = dA[grow * 2 + 1] - dB[grow * 2 + 1];
        #pragma unroll
        for (int ei = 0; ei < EE; ei++) {
            float v = fmaf(W_emb[ei * 2 + 0], dx,
                      fmaf(W_emb[ei * 2 + 1], dy, b_emb[ei]));
            e_s[tid * EE + ei] = fmaxf(v, 0.0f);
        }
    }
    // stage h block (identity copy of permuted layout; coalesced)
    if (is_first) {
        for (int i = tid; i < MT * HH / 4; i += NTHR)
            ((float4*)hs_s)[i] = make_float4(0.f, 0.f, 0.f, 0.f);
    } else {
        const float4* src = (const float4*)(g_h + (size_t)m0 * HH);
        for (int i = tid; i < MT * HH / 4; i += NTHR)
            ((float4*)hs_s)[i] = src[i];
    }
    __syncthreads();

    // build A fragments (fp16), fragment-linear: (mt,kt) block 512B,
    // lane L2 has 4 regs. reg r: row += (r&1)*8, k += (r>>1)*8.
    for (int idx = tid; idx < 16 * 9 * 128; idx += NTHR) {
        int r = idx & 3;
        int L2 = (idx >> 2) & 31;
        int kt = (idx >> 7) % 9;
        int mt = idx / (128 * 9);
        int row = mt * 16 + (L2 >> 2) + (r & 1) * 8;
        int k0 = kt * 16 + (L2 & 3) * 2 + (r >> 1) * 8;
        float v0, v1;
        if (k0 < HH) {
            int p = hperm(row, k0);
            v0 = hs_s[p];
            v1 = hs_s[p + 2];      // k0+1 flips al: +2 lanes
        } else {
            v0 = e_s[row * EE + (k0 - HH)];
            v1 = e_s[row * EE + (k0 - HH) + 1];
        }
        ((uint32_t*)(smem + SM_AF))[(mt * 9 + kt) * 128 + L2 * 4 + r] =
            packh2(v0, v1);
    }
    __syncthreads();   // hs_s dead; B buffers may now be filled

    // prefetch B chunk 0
    {
        const unsigned char* src = (const unsigned char*)g_Bfrag;
        for (int i = tid; i < CHUNKB / 16; i += NTHR)
            cp16(sbase + SM_B0 + i * 16, src + i * 16);
        CP_COMMIT();
    }

    // lane geometry
    const int a_lane = (L & 3) >> 1;            // quad index within ntile
    const int odd = L & 1;                      // 0: rows g (i,f own); 1: g+8
    const int row_lane = m0 + w * 16 + (L >> 2) + odd * 8;
    const uint32_t afw = sbase + SM_AF + (uint32_t)(w * 9) * 512 + L * 16;
    const size_t pb = (size_t)m0 * HH + (size_t)w * 32 + L;  // permuted base
    float s0 = 0.0f, s1 = 0.0f;

    for (int c = 0; c < 8; c++) {
        if (c + 1 < 8) {
            const unsigned char* src =
                (const unsigned char*)g_Bfrag + (c + 1) * CHUNKB;
            uint32_t dst = sbase + (((c + 1) & 1) ? SM_B1 : SM_B0);
            for (int i = tid; i < CHUNKB / 16; i += NTHR)
                cp16(dst + i * 16, src + i * 16);
            CP_COMMIT();
            cp_wait<1>();
        } else {
            cp_wait<0>();
        }
        __syncthreads();

        // preload this chunk's c-state (8 coalesced LDG)
        float creg[8];
        #pragma unroll
        for (int u = 0; u < 8; u++)
            creg[u] = is_first ? 0.0f : g_c[pb + (size_t)(c * 8 + u) * 512];

        const uint32_t bb = sbase + ((c & 1) ? SM_B1 : SM_B0);
        #pragma unroll
        for (int tg = 0; tg < 2; tg++) {
            float D[4][4];
            #pragma unroll
            for (int t = 0; t < 4; t++)
                #pragma unroll
                for (int q = 0; q < 4; q++) D[t][q] = 0.0f;

            #pragma unroll
            for (int kt = 0; kt < 9; kt++) {
                uint32_t a[4];
                lds128(a, afw + kt * 512);
                #pragma unroll
                for (int t2 = 0; t2 < 2; t2++) {
                    int ntp = tg * 2 + t2;
                    uint32_t b4[4];   // [ntEven | ntOdd] fragments
                    lds128(b4, bb + (uint32_t)((ntp * 9 + kt) * 512) + L * 16);
                    mma16816(D[t2 * 2 + 0], a, b4);
                    mma16816(D[t2 * 2 + 1], a, b4 + 2);
                }
            }
            // epilogue: quad exchange + cell update (1 unit-row per lane/tile)
            #pragma unroll
            for (int t = 0; t < 4; t++) {
                int nt = tg * 4 + t;
                int j = c * 16 + 2 * nt + a_lane;
                float e0 = __shfl_xor_sync(0xFFFFFFFFu, D[t][0], 1);
                float e1 = __shfl_xor_sync(0xFFFFFFFFu, D[t][1], 1);
                float e2 = __shfl_xor_sync(0xFFFFFFFFu, D[t][2], 1);
                float e3 = __shfl_xor_sync(0xFFFFFFFFu, D[t][3], 1);
                float gi = odd ? e2 : D[t][0];
                float gf = odd ? e3 : D[t][1];
                float gg = odd ? D[t][2] : e0;
                float go = odd ? D[t][3] : e1;
                float4 bq = *(const float4*)(bq4_s + j * 4);
                float iv = fsig(gi + bq.x);
                float fv = fsig(gf + bq.y);
                float gv = tanh_hw(gg + bq.z);
                float ov = fsig(go + bq.w);
                float c2 = fmaf(fv, creg[tg * 4 + t], iv * gv);
                float h2 = ov * tanh_hw(c2);
                size_t gidx = pb + (size_t)(c * 8 + nt) * 512;  // coalesced
                g_c[gidx] = c2;
                g_h[gidx] = h2;
                s0 = fmaf(h2, wout_s[j], s0);
                s1 = fmaf(h2, wout_s[128 + j], s1);
            }
        }
        __syncthreads();   // all warps done with this chunk's B buffer
    }

    // readout: combine the two lanes (a=0/a=1) sharing a row, then write
    s0 += __shfl_xor_sync(0xFFFFFFFFu, s0, 2);
    s1 += __shfl_xor_sync(0xFFFFFFFFu, s1, 2);
    if ((L & 3) < 2) {
        outp[row_lane * 2 + 0] = dA[row_lane * 2 + 0] + s0 + b_out[0];
        outp[row_lane * 2 + 1] = dA[row_lane * 2 + 1] + s1 + b_out[1];
    }
}

// ---------------------------------------------------------------------------
extern "C" void kernel_launch(void* const* d_in, const int* in_sizes, int n_in,
                              void* d_out, int out_size) {
    const float* observed = (const float*)d_in[0];
    const float* W_emb    = (const float*)d_in[1];
    const float* b_emb    = (const float*)d_in[2];
    const float* W_ih     = (const float*)d_in[3];
    const float* b_ih     = (const float*)d_in[4];
    const float* W_hh     = (const float*)d_in[5];
    const float* b_hh     = (const float*)d_in[6];
    const float* W_out    = (const float*)d_in[7];
    const float* b_out    = (const float*)d_in[8];
    float* out = (float*)d_out;

    static bool attr_set = false;
    if (!attr_set) {
        cudaFuncSetAttribute(lstm_step,
                             cudaFuncAttributeMaxDynamicSharedMemorySize, SMEM_SZ);
        attr_set = true;
    }

    prep_kernel<<<96, 256>>>(W_ih, b_ih, W_hh, b_hh);

    const size_t rs = (size_t)BB * 2;
    // observation phase: t = 1..8 -> out rows 0..7
    for (int t = 1; t < NOBS; t++) {
        lstm_step<<<NCTA, NTHR, SMEM_SZ>>>(
            observed + (size_t)t * rs, observed + (size_t)(t - 1) * rs,
            out + (size_t)(t - 1) * rs,
            W_emb, b_emb, W_out, b_out, (t == 1) ? 1 : 0);
    }
    // prediction phase: out rows 8..18
    for (int r = NOBS - 1; r < NOUT; r++) {
        lstm_step<<<NCTA, NTHR, SMEM_SZ>>>(
            out + (size_t)(r - 1) * rs, out + (size_t)(r - 2) * rs,
            out + (size_t)r * rs,
            W_emb, b_emb, W_out, b_out, 0);
    }
}